// round 2
// baseline (speedup 1.0000x reference)
#include <cuda_runtime.h>
#include <cuda_bf16.h>
#include <math.h>

// ---------------- problem constants ----------------
#define NSAMP   1024          // B*P = 2*512
#define CIN     512
#define CMID    1024
#define HW      49
#define NCLS    9
#define PRE_K   512
#define DETS    100
#define IMGW    640.0f
#define IMGH    384.0f

// output layout (float32, concatenated reference outputs)
#define O_EMB   ((size_t)0)
#define O_CLS   ((size_t)51380224)            // 1024*1024*49
#define O_REG   ((size_t)51389440)            // + 1024*9
#define O_BOX   ((size_t)51426304)            // + 1024*36
#define O_SCO   ((size_t)51427104)            // + 2*100*4
#define O_LAB   ((size_t)51427304)
#define O_VAL   ((size_t)51427504)

#define SMEM_BYTES (512*81*4)                 // 165888 padded tile

// ---------------- scratch (device globals; no allocation) ----------------
__device__ float g_h[(size_t)NSAMP*CMID*HW];      // conv1 output (205 MB)
__device__ float g_w1t[(size_t)CIN*9*CMID];       // [ci*9+k][co]
__device__ float g_w2t[(size_t)CMID*9*CMID];
__device__ float g_wdt[(size_t)CIN*CMID];
__device__ float g_flat[(size_t)NSAMP*CMID];
__device__ float g_cls[NSAMP*NCLS];
__device__ float g_reg[NSAMP*NCLS*4];
__device__ float g_boxes[NSAMP*NCLS*4];
__device__ float g_scores[NSAMP*NCLS];

// ---------------- f32x2 helpers ----------------
// fma.rn.f32x2 d,a,b,c  computes d = a*b + c (elementwise on packed pair)
__device__ __forceinline__ unsigned long long fma2(unsigned long long a,
                                                   unsigned long long b,
                                                   unsigned long long c) {
    unsigned long long d;
    asm("fma.rn.f32x2 %0, %1, %2, %3;" : "=l"(d) : "l"(a), "l"(b), "l"(c));
    return d;
}
__device__ __forceinline__ unsigned long long dup2(float v) {
    unsigned long long d;
    asm("mov.b64 %0, {%1, %1};" : "=l"(d) : "f"(v));
    return d;
}
__device__ __forceinline__ void unpack2(unsigned long long a, float& lo, float& hi) {
    asm("mov.b64 {%0, %1}, %2;" : "=f"(lo), "=f"(hi) : "l"(a));
}

// ---------------- weight transposes ----------------
__global__ void tr_w1(const float* __restrict__ w) {
    int idx = blockIdx.x * blockDim.x + threadIdx.x;
    if (idx >= CIN * 9 * CMID) return;
    int co = idx & 1023; int r = idx >> 10; int ci = r / 9; int k = r - ci * 9;
    g_w1t[idx] = w[((size_t)co * CIN + ci) * 9 + k];
}
__global__ void tr_w2(const float* __restrict__ w) {
    int idx = blockIdx.x * blockDim.x + threadIdx.x;
    if (idx >= CMID * 9 * CMID) return;
    int co = idx & 1023; int r = idx >> 10; int ci = r / 9; int k = r - ci * 9;
    g_w2t[idx] = w[((size_t)co * CMID + ci) * 9 + k];
}
__global__ void tr_wd(const float* __restrict__ w) {
    int idx = blockIdx.x * blockDim.x + threadIdx.x;
    if (idx >= CIN * CMID) return;
    int co = idx & 1023; int ci = idx >> 10;
    g_wdt[idx] = w[(size_t)co * CIN + ci];
}

// ---------------- conv helpers ----------------
// padded tile: xs[ci*81 + yy*9 + xx] = src[ci*49 + (yy-1)*7 + (xx-1)], 0 on border
__device__ __forceinline__ void load_padded(float* xs, const float* __restrict__ src, int tid) {
    for (int i = tid; i < 512 * 81; i += 256) {
        int ci = i / 81; int r = i - ci * 81; int yy = r / 9; int xx = r - yy * 9;
        float v = 0.f;
        if (yy >= 1 && yy <= 7 && xx >= 1 && xx <= 7)
            v = src[ci * 49 + (yy - 1) * 7 + (xx - 1)];
        xs[i] = v;
    }
}

// accumulate a 512-channel chunk of a 3x3 conv into 49 f32x2 accumulators
__device__ __forceinline__ void accum_chunk(const float* __restrict__ xs,
                                            const float* __restrict__ wbase,
                                            unsigned long long (&acc)[49]) {
    for (int ci = 0; ci < 512; ci++) {
        const float* wp = wbase + (size_t)ci * 9 * 1024;
        unsigned long long wv[9];
        #pragma unroll
        for (int k = 0; k < 9; k++)
            wv[k] = *reinterpret_cast<const unsigned long long*>(wp + (size_t)k * 1024);
        const float* xr = xs + ci * 81;
        unsigned long long rwd[3][9];
        #pragma unroll
        for (int c = 0; c < 9; c++) { rwd[0][c] = dup2(xr[c]); rwd[1][c] = dup2(xr[9 + c]); }
        #pragma unroll
        for (int y = 0; y < 7; y++) {
            #pragma unroll
            for (int c = 0; c < 9; c++) rwd[(y + 2) % 3][c] = dup2(xr[(y + 2) * 9 + c]);
            #pragma unroll
            for (int xq = 0; xq < 7; xq++) {
                unsigned long long a = acc[y * 7 + xq];
                #pragma unroll
                for (int t = 0; t < 9; t++)
                    a = fma2(wv[t], rwd[(y + t / 3) % 3][(t % 3) + xq], a);   // acc += w*x
                acc[y * 7 + xq] = a;
            }
        }
    }
}

// ---------------- conv1 + relu -> g_h ----------------
__global__ void __launch_bounds__(256, 1) conv1_kernel(const float* __restrict__ x) {
    extern __shared__ float xs[];
    int n = blockIdx.x;
    int co = (blockIdx.y << 9) + (threadIdx.x << 1);
    load_padded(xs, x + (size_t)n * CIN * HW, threadIdx.x);
    __syncthreads();
    unsigned long long acc[49];
    #pragma unroll
    for (int p = 0; p < 49; p++) acc[p] = 0ull;
    accum_chunk(xs, g_w1t + co, acc);
    float* hp = g_h + ((size_t)n * CMID + co) * HW;
    #pragma unroll
    for (int p = 0; p < 49; p++) {
        float lo, hi; unpack2(acc[p], lo, hi);
        hp[p]      = fmaxf(lo, 0.f);
        hp[HW + p] = fmaxf(hi, 0.f);
    }
}

// ------- conv2(h) + 1x1 shortcut(x) + relu -> embedded (d_out) + avg-pool -> g_flat -------
__global__ void __launch_bounds__(256, 1) conv2_kernel(const float* __restrict__ x,
                                                       float* __restrict__ d_out) {
    extern __shared__ float xs[];
    int n = blockIdx.x;
    int co = (blockIdx.y << 9) + (threadIdx.x << 1);
    unsigned long long acc[49];
    #pragma unroll
    for (int p = 0; p < 49; p++) acc[p] = 0ull;

    const float* hsrc = g_h + (size_t)n * CMID * HW;
    for (int half = 0; half < 2; half++) {
        load_padded(xs, hsrc + (size_t)half * 512 * HW, threadIdx.x);
        __syncthreads();
        accum_chunk(xs, g_w2t + (size_t)half * 512 * 9 * 1024 + co, acc);
        __syncthreads();
    }
    // 1x1 shortcut
    {
        const float* xsrc = x + (size_t)n * CIN * HW;
        for (int i = threadIdx.x; i < 512 * HW; i += 256) xs[i] = xsrc[i];
        __syncthreads();
        for (int ci = 0; ci < 512; ci++) {
            unsigned long long wv =
                *reinterpret_cast<const unsigned long long*>(g_wdt + (size_t)ci * 1024 + co);
            const float* xr = xs + ci * HW;
            #pragma unroll
            for (int p = 0; p < 49; p++) acc[p] = fma2(wv, dup2(xr[p]), acc[p]);  // acc += w*x
        }
    }
    float s0 = 0.f, s1 = 0.f;
    float* ep = d_out + O_EMB + ((size_t)n * CMID + co) * HW;
    #pragma unroll
    for (int p = 0; p < 49; p++) {
        float lo, hi; unpack2(acc[p], lo, hi);
        lo = fmaxf(lo, 0.f); hi = fmaxf(hi, 0.f);
        ep[p] = lo; ep[HW + p] = hi;
        s0 += lo; s1 += hi;
    }
    g_flat[(size_t)n * CMID + co]     = s0 / 49.0f;
    g_flat[(size_t)n * CMID + co + 1] = s1 / 49.0f;
}

// ---------------- head GEMMs: cls_scores [N,9], bbox_reg [N,36] ----------------
__global__ void head_kernel(const float* __restrict__ cls_w, const float* __restrict__ cls_b,
                            const float* __restrict__ reg_w, const float* __restrict__ reg_b,
                            float* __restrict__ d_out) {
    int n = blockIdx.x;
    int w = threadIdx.x >> 5, lane = threadIdx.x & 31;
    const float* f = g_flat + (size_t)n * CMID;
    for (int o = w; o < 45; o += 8) {
        const float* wr; float bias;
        if (o < NCLS) { wr = cls_w + (size_t)o * CMID; bias = cls_b[o]; }
        else          { wr = reg_w + (size_t)(o - NCLS) * CMID; bias = reg_b[o - NCLS]; }
        float acc = 0.f;
        for (int k = lane; k < CMID; k += 32) acc += f[k] * wr[k];
        #pragma unroll
        for (int d = 16; d; d >>= 1) acc += __shfl_xor_sync(0xffffffffu, acc, d);
        if (lane == 0) {
            float v = acc + bias;
            if (o < NCLS) { g_cls[n * NCLS + o] = v; d_out[O_CLS + n * NCLS + o] = v; }
            else { g_reg[n * 36 + (o - NCLS)] = v; d_out[O_REG + n * 36 + (o - NCLS)] = v; }
        }
    }
}

// ---------------- softmax + box decode + clip ----------------
__global__ void decode_kernel(const float* __restrict__ proposals) {
    int n = blockIdx.x; int lane = threadIdx.x;      // 32 threads
    float logit = (lane < NCLS) ? g_cls[n * NCLS + lane] : -INFINITY;
    float m = logit;
    #pragma unroll
    for (int d = 16; d; d >>= 1) m = fmaxf(m, __shfl_xor_sync(0xffffffffu, m, d));
    float e = (lane < NCLS) ? expf(logit - m) : 0.f;
    float s = e;
    #pragma unroll
    for (int d = 16; d; d >>= 1) s += __shfl_xor_sync(0xffffffffu, s, d);
    if (lane < NCLS) {
        g_scores[n * NCLS + lane] = e / s;
        const float* pr = proposals + (size_t)n * 4;
        float pw = pr[2] - pr[0], ph = pr[3] - pr[1];
        float pcx = pr[0] + 0.5f * pw, pcy = pr[1] + 0.5f * ph;
        const float* rr = g_reg + n * 36 + lane * 4;
        float dx = rr[0] / 10.0f, dy = rr[1] / 10.0f;
        float dw = fminf(rr[2] / 5.0f, 4.135166556742356f);
        float dh = fminf(rr[3] / 5.0f, 4.135166556742356f);
        float ncx = dx * pw + pcx, ncy = dy * ph + pcy;
        float nw = expf(dw) * pw, nh = expf(dh) * ph;
        float b0 = fminf(fmaxf(ncx - 0.5f * nw, 0.f), IMGW);
        float b1 = fminf(fmaxf(ncy - 0.5f * nh, 0.f), IMGH);
        float b2 = fminf(fmaxf(ncx + 0.5f * nw, 0.f), IMGW);
        float b3 = fminf(fmaxf(ncy + 0.5f * nh, 0.f), IMGH);
        float* bp = g_boxes + (size_t)(n * NCLS + lane) * 4;
        bp[0] = b0; bp[1] = b1; bp[2] = b2; bp[3] = b3;
    }
}

// ---------------- per-image: filter -> sort(4096) -> NMS(512) -> top-100 ----------------
__global__ void __launch_bounds__(512) nms_kernel(float* __restrict__ d_out) {
    __shared__ float skey[4096];
    __shared__ int   sidx[4096];
    __shared__ float sbox[PRE_K * 4];   // boxes with class offset applied (as reference)
    __shared__ int   slab[PRE_K];
    __shared__ int   skeep[PRE_K];
    __shared__ int   swsum[16];

    int img = blockIdx.x; int tid = threadIdx.x;

    // candidates: j = p*8 + (c-1), c in 1..8
    for (int j = tid; j < 4096; j += 512) {
        int p = j >> 3, c = (j & 7) + 1;
        int n = img * 512 + p;
        float s = g_scores[n * NCLS + c];
        const float* bb = g_boxes + (size_t)(n * NCLS + c) * 4;
        bool valid = (s > 0.05f) && ((bb[2] - bb[0]) >= 0.01f) && ((bb[3] - bb[1]) >= 0.01f);
        skey[j] = valid ? s : -INFINITY;
        sidx[j] = j;
    }
    __syncthreads();

    // bitonic sort, best-first (score desc, index asc on ties -> matches top_k)
    for (int k = 2; k <= 4096; k <<= 1) {
        for (int j2 = k >> 1; j2 > 0; j2 >>= 1) {
            for (int i = tid; i < 4096; i += 512) {
                int ixj = i ^ j2;
                if (ixj > i) {
                    float ka = skey[i], kb = skey[ixj];
                    int ia = sidx[i], ib = sidx[ixj];
                    bool a_first = (ka > kb) || (ka == kb && ia < ib);
                    bool up = ((i & k) == 0);
                    if (up ? !a_first : a_first) {
                        skey[i] = kb; skey[ixj] = ka;
                        sidx[i] = ib; sidx[ixj] = ia;
                    }
                }
            }
            __syncthreads();
        }
    }

    // top-512: stage offset boxes (reference computes IoU on boxes + label*641)
    if (tid < PRE_K) {
        float s = skey[tid];
        int j = sidx[tid];
        int p = j >> 3, c = (j & 7) + 1;
        int n = img * 512 + p;
        const float* bb = g_boxes + (size_t)(n * NCLS + c) * 4;
        float off = 641.0f * (float)c;
        sbox[tid * 4 + 0] = bb[0] + off;
        sbox[tid * 4 + 1] = bb[1] + off;
        sbox[tid * 4 + 2] = bb[2] + off;
        sbox[tid * 4 + 3] = bb[3] + off;
        slab[tid] = c;
        skeep[tid] = (s != -INFINITY) ? 1 : 0;
    }
    __syncthreads();

    // greedy NMS (sequential over i, parallel over j = tid)
    for (int i = 0; i < PRE_K; i++) {
        if (skeep[i]) {
            int j = tid;
            if (j > i && skeep[j]) {
                float ax0 = sbox[i*4], ay0 = sbox[i*4+1], ax1 = sbox[i*4+2], ay1 = sbox[i*4+3];
                float bx0 = sbox[j*4], by0 = sbox[j*4+1], bx1 = sbox[j*4+2], by1 = sbox[j*4+3];
                float areaA = (ax1 - ax0) * (ay1 - ay0);
                float areaB = (bx1 - bx0) * (by1 - by0);
                float iw = fmaxf(fminf(ax1, bx1) - fmaxf(ax0, bx0), 0.f);
                float ih = fmaxf(fminf(ay1, by1) - fmaxf(ay0, by0), 0.f);
                float inter = iw * ih;
                float iou = inter / fmaxf(areaA + areaB - inter, 1e-8f);
                if (iou > 0.5f) skeep[j] = 0;
            }
        }
        __syncthreads();
    }

    // rank of kept entries (order preserved = descending score = reference top_k)
    int keepflag = (tid < PRE_K) ? skeep[tid] : 0;
    unsigned mask = __ballot_sync(0xffffffffu, keepflag != 0);
    int lane = tid & 31, wid = tid >> 5;
    if (lane == 0) swsum[wid] = __popc(mask);
    __syncthreads();
    int base = 0;
    for (int w = 0; w < wid; w++) base += swsum[w];
    int rank = base + __popc(mask & ((1u << lane) - 1u));

    float* dbx = d_out + O_BOX + (size_t)img * DETS * 4;
    float* dsc = d_out + O_SCO + (size_t)img * DETS;
    float* dlb = d_out + O_LAB + (size_t)img * DETS;
    float* dvl = d_out + O_VAL + (size_t)img * DETS;
    for (int i = tid; i < DETS; i += 512) {
        dbx[i*4+0] = 0.f; dbx[i*4+1] = 0.f; dbx[i*4+2] = 0.f; dbx[i*4+3] = 0.f;
        dsc[i] = 0.f; dlb[i] = 0.f; dvl[i] = 0.f;
    }
    __syncthreads();
    if (keepflag && rank < DETS) {
        int j = sidx[tid];
        int p = j >> 3, c = (j & 7) + 1;
        int n = img * 512 + p;
        const float* bb = g_boxes + (size_t)(n * NCLS + c) * 4;
        dbx[rank*4+0] = bb[0]; dbx[rank*4+1] = bb[1];
        dbx[rank*4+2] = bb[2]; dbx[rank*4+3] = bb[3];
        dsc[rank] = skey[tid];
        dlb[rank] = (float)c;
        dvl[rank] = 1.0f;
    }
}

// ---------------- launch ----------------
extern "C" void kernel_launch(void* const* d_in, const int* in_sizes, int n_in,
                              void* d_out, int out_size) {
    const float* feats     = (const float*)d_in[0];
    const float* proposals = (const float*)d_in[1];
    const float* w1        = (const float*)d_in[2];
    const float* w2        = (const float*)d_in[3];
    const float* wd        = (const float*)d_in[4];
    const float* cls_w     = (const float*)d_in[5];
    const float* cls_b     = (const float*)d_in[6];
    const float* reg_w     = (const float*)d_in[7];
    const float* reg_b     = (const float*)d_in[8];
    float* out = (float*)d_out;

    cudaFuncSetAttribute(conv1_kernel, cudaFuncAttributeMaxDynamicSharedMemorySize, SMEM_BYTES);
    cudaFuncSetAttribute(conv2_kernel, cudaFuncAttributeMaxDynamicSharedMemorySize, SMEM_BYTES);

    tr_w1<<<(CIN * 9 * CMID + 255) / 256, 256>>>(w1);
    tr_w2<<<(CMID * 9 * CMID + 255) / 256, 256>>>(w2);
    tr_wd<<<(CIN * CMID + 255) / 256, 256>>>(wd);

    conv1_kernel<<<dim3(NSAMP, 2), 256, SMEM_BYTES>>>(feats);
    conv2_kernel<<<dim3(NSAMP, 2), 256, SMEM_BYTES>>>(feats, out);

    head_kernel<<<NSAMP, 256>>>(cls_w, cls_b, reg_w, reg_b, out);
    decode_kernel<<<NSAMP, 32>>>(proposals);
    nms_kernel<<<2, 512>>>(out);
}

// round 3
// speedup vs baseline: 1.5848x; 1.5848x over previous
#include <cuda_runtime.h>
#include <cuda_bf16.h>
#include <math.h>

// ---------------- problem constants ----------------
#define NSAMP   1024          // B*P = 2*512
#define CIN     512
#define CMID    1024
#define HW      49
#define NCLS    9
#define PRE_K   512
#define DETS    100
#define IMGW    640.0f
#define IMGH    384.0f

// output layout (float32, concatenated reference outputs)
#define O_EMB   ((size_t)0)
#define O_CLS   ((size_t)51380224)            // 1024*1024*49
#define O_REG   ((size_t)51389440)            // + 1024*9
#define O_BOX   ((size_t)51426304)            // + 1024*36
#define O_SCO   ((size_t)51427104)            // + 2*100*4
#define O_LAB   ((size_t)51427304)
#define O_VAL   ((size_t)51427504)

#define SMEM_BYTES (512*81*4)                 // 165888 padded tile

// ---------------- scratch (device globals; no allocation) ----------------
__device__ float g_h[(size_t)NSAMP*CMID*HW];      // conv1 output (205 MB)
__device__ float g_w1t[(size_t)CIN*9*CMID];       // [ci*9+k][co]
__device__ float g_w2t[(size_t)CMID*9*CMID];
__device__ float g_wdt[(size_t)CIN*CMID];
__device__ float g_flat[(size_t)NSAMP*CMID];
__device__ float g_cls[NSAMP*NCLS];
__device__ float g_reg[NSAMP*NCLS*4];
__device__ float g_boxes[NSAMP*NCLS*4];
__device__ float g_scores[NSAMP*NCLS];

// ---------------- f32x2 helpers ----------------
// fma.rn.f32x2 d,a,b,c  computes d = a*b + c (elementwise on packed pair)
__device__ __forceinline__ unsigned long long fma2(unsigned long long a,
                                                   unsigned long long b,
                                                   unsigned long long c) {
    unsigned long long d;
    asm("fma.rn.f32x2 %0, %1, %2, %3;" : "=l"(d) : "l"(a), "l"(b), "l"(c));
    return d;
}
__device__ __forceinline__ unsigned long long dup2(float v) {
    unsigned long long d;
    asm("mov.b64 %0, {%1, %1};" : "=l"(d) : "f"(v));
    return d;
}
__device__ __forceinline__ void unpack2(unsigned long long a, float& lo, float& hi) {
    asm("mov.b64 {%0, %1}, %2;" : "=f"(lo), "=f"(hi) : "l"(a));
}

// ---------------- weight transposes ----------------
__global__ void tr_w1(const float* __restrict__ w) {
    int idx = blockIdx.x * blockDim.x + threadIdx.x;
    if (idx >= CIN * 9 * CMID) return;
    int co = idx & 1023; int r = idx >> 10; int ci = r / 9; int k = r - ci * 9;
    g_w1t[idx] = w[((size_t)co * CIN + ci) * 9 + k];
}
__global__ void tr_w2(const float* __restrict__ w) {
    int idx = blockIdx.x * blockDim.x + threadIdx.x;
    if (idx >= CMID * 9 * CMID) return;
    int co = idx & 1023; int r = idx >> 10; int ci = r / 9; int k = r - ci * 9;
    g_w2t[idx] = w[((size_t)co * CMID + ci) * 9 + k];
}
__global__ void tr_wd(const float* __restrict__ w) {
    int idx = blockIdx.x * blockDim.x + threadIdx.x;
    if (idx >= CIN * CMID) return;
    int co = idx & 1023; int ci = idx >> 10;
    g_wdt[idx] = w[(size_t)co * CIN + ci];
}

// ---------------- conv helpers ----------------
// padded tile: xs[ci*81 + yy*9 + xx] = src[ci*49 + (yy-1)*7 + (xx-1)], 0 on border
__device__ __forceinline__ void load_padded(float* xs, const float* __restrict__ src, int tid) {
    for (int i = tid; i < 512 * 81; i += 256) {
        int ci = i / 81; int r = i - ci * 81; int yy = r / 9; int xx = r - yy * 9;
        float v = 0.f;
        if (yy >= 1 && yy <= 7 && xx >= 1 && xx <= 7)
            v = src[ci * 49 + (yy - 1) * 7 + (xx - 1)];
        xs[i] = v;
    }
}

// accumulate a 512-channel chunk of a 3x3 conv into 49 f32x2 accumulators
__device__ __forceinline__ void accum_chunk(const float* __restrict__ xs,
                                            const float* __restrict__ wbase,
                                            unsigned long long (&acc)[49]) {
    for (int ci = 0; ci < 512; ci++) {
        const float* wp = wbase + (size_t)ci * 9 * 1024;
        unsigned long long wv[9];
        #pragma unroll
        for (int k = 0; k < 9; k++)
            wv[k] = *reinterpret_cast<const unsigned long long*>(wp + (size_t)k * 1024);
        const float* xr = xs + ci * 81;
        unsigned long long rwd[3][9];
        #pragma unroll
        for (int c = 0; c < 9; c++) { rwd[0][c] = dup2(xr[c]); rwd[1][c] = dup2(xr[9 + c]); }
        #pragma unroll
        for (int y = 0; y < 7; y++) {
            #pragma unroll
            for (int c = 0; c < 9; c++) rwd[(y + 2) % 3][c] = dup2(xr[(y + 2) * 9 + c]);
            #pragma unroll
            for (int xq = 0; xq < 7; xq++) {
                unsigned long long a = acc[y * 7 + xq];
                #pragma unroll
                for (int t = 0; t < 9; t++)
                    a = fma2(wv[t], rwd[(y + t / 3) % 3][(t % 3) + xq], a);   // acc += w*x
                acc[y * 7 + xq] = a;
            }
        }
    }
}

// ---------------- conv1 + relu -> g_h ----------------
__global__ void __launch_bounds__(256, 1) conv1_kernel(const float* __restrict__ x) {
    extern __shared__ float xs[];
    int n = blockIdx.x;
    int co = (blockIdx.y << 9) + (threadIdx.x << 1);
    load_padded(xs, x + (size_t)n * CIN * HW, threadIdx.x);
    __syncthreads();
    unsigned long long acc[49];
    #pragma unroll
    for (int p = 0; p < 49; p++) acc[p] = 0ull;
    accum_chunk(xs, g_w1t + co, acc);
    float* hp = g_h + ((size_t)n * CMID + co) * HW;
    #pragma unroll
    for (int p = 0; p < 49; p++) {
        float lo, hi; unpack2(acc[p], lo, hi);
        hp[p]      = fmaxf(lo, 0.f);
        hp[HW + p] = fmaxf(hi, 0.f);
    }
}

// ------- conv2(h) + 1x1 shortcut(x) + relu -> embedded (d_out) + avg-pool -> g_flat -------
__global__ void __launch_bounds__(256, 1) conv2_kernel(const float* __restrict__ x,
                                                       float* __restrict__ d_out) {
    extern __shared__ float xs[];
    int n = blockIdx.x;
    int co = (blockIdx.y << 9) + (threadIdx.x << 1);
    unsigned long long acc[49];
    #pragma unroll
    for (int p = 0; p < 49; p++) acc[p] = 0ull;

    const float* hsrc = g_h + (size_t)n * CMID * HW;
    for (int half = 0; half < 2; half++) {
        load_padded(xs, hsrc + (size_t)half * 512 * HW, threadIdx.x);
        __syncthreads();
        accum_chunk(xs, g_w2t + (size_t)half * 512 * 9 * 1024 + co, acc);
        __syncthreads();
    }
    // 1x1 shortcut
    {
        const float* xsrc = x + (size_t)n * CIN * HW;
        for (int i = threadIdx.x; i < 512 * HW; i += 256) xs[i] = xsrc[i];
        __syncthreads();
        for (int ci = 0; ci < 512; ci++) {
            unsigned long long wv =
                *reinterpret_cast<const unsigned long long*>(g_wdt + (size_t)ci * 1024 + co);
            const float* xr = xs + ci * HW;
            #pragma unroll
            for (int p = 0; p < 49; p++) acc[p] = fma2(wv, dup2(xr[p]), acc[p]);  // acc += w*x
        }
    }
    float s0 = 0.f, s1 = 0.f;
    float* ep = d_out + O_EMB + ((size_t)n * CMID + co) * HW;
    #pragma unroll
    for (int p = 0; p < 49; p++) {
        float lo, hi; unpack2(acc[p], lo, hi);
        lo = fmaxf(lo, 0.f); hi = fmaxf(hi, 0.f);
        ep[p] = lo; ep[HW + p] = hi;
        s0 += lo; s1 += hi;
    }
    g_flat[(size_t)n * CMID + co]     = s0 / 49.0f;
    g_flat[(size_t)n * CMID + co + 1] = s1 / 49.0f;
}

// ---------------- head GEMMs: cls_scores [N,9], bbox_reg [N,36] ----------------
__global__ void head_kernel(const float* __restrict__ cls_w, const float* __restrict__ cls_b,
                            const float* __restrict__ reg_w, const float* __restrict__ reg_b,
                            float* __restrict__ d_out) {
    int n = blockIdx.x;
    int w = threadIdx.x >> 5, lane = threadIdx.x & 31;
    const float* f = g_flat + (size_t)n * CMID;
    for (int o = w; o < 45; o += 8) {
        const float* wr; float bias;
        if (o < NCLS) { wr = cls_w + (size_t)o * CMID; bias = cls_b[o]; }
        else          { wr = reg_w + (size_t)(o - NCLS) * CMID; bias = reg_b[o - NCLS]; }
        float acc = 0.f;
        for (int k = lane; k < CMID; k += 32) acc += f[k] * wr[k];
        #pragma unroll
        for (int d = 16; d; d >>= 1) acc += __shfl_xor_sync(0xffffffffu, acc, d);
        if (lane == 0) {
            float v = acc + bias;
            if (o < NCLS) { g_cls[n * NCLS + o] = v; d_out[O_CLS + n * NCLS + o] = v; }
            else { g_reg[n * 36 + (o - NCLS)] = v; d_out[O_REG + n * 36 + (o - NCLS)] = v; }
        }
    }
}

// ---------------- softmax + box decode + clip ----------------
__global__ void decode_kernel(const float* __restrict__ proposals) {
    int n = blockIdx.x; int lane = threadIdx.x;      // 32 threads
    float logit = (lane < NCLS) ? g_cls[n * NCLS + lane] : -INFINITY;
    float m = logit;
    #pragma unroll
    for (int d = 16; d; d >>= 1) m = fmaxf(m, __shfl_xor_sync(0xffffffffu, m, d));
    float e = (lane < NCLS) ? expf(logit - m) : 0.f;
    float s = e;
    #pragma unroll
    for (int d = 16; d; d >>= 1) s += __shfl_xor_sync(0xffffffffu, s, d);
    if (lane < NCLS) {
        g_scores[n * NCLS + lane] = e / s;
        const float* pr = proposals + (size_t)n * 4;
        float pw = pr[2] - pr[0], ph = pr[3] - pr[1];
        float pcx = pr[0] + 0.5f * pw, pcy = pr[1] + 0.5f * ph;
        const float* rr = g_reg + n * 36 + lane * 4;
        float dx = rr[0] / 10.0f, dy = rr[1] / 10.0f;
        float dw = fminf(rr[2] / 5.0f, 4.135166556742356f);
        float dh = fminf(rr[3] / 5.0f, 4.135166556742356f);
        float ncx = dx * pw + pcx, ncy = dy * ph + pcy;
        float nw = expf(dw) * pw, nh = expf(dh) * ph;
        float b0 = fminf(fmaxf(ncx - 0.5f * nw, 0.f), IMGW);
        float b1 = fminf(fmaxf(ncy - 0.5f * nh, 0.f), IMGH);
        float b2 = fminf(fmaxf(ncx + 0.5f * nw, 0.f), IMGW);
        float b3 = fminf(fmaxf(ncy + 0.5f * nh, 0.f), IMGH);
        float* bp = g_boxes + (size_t)(n * NCLS + lane) * 4;
        bp[0] = b0; bp[1] = b1; bp[2] = b2; bp[3] = b3;
    }
}

// ---------------- per-image: filter -> sort(4096) -> NMS(512) -> top-100 ----------------
__global__ void __launch_bounds__(512) nms_kernel(float* __restrict__ d_out) {
    __shared__ float skey[4096];
    __shared__ int   sidx[4096];
    __shared__ float sbox[PRE_K * 4];   // boxes with class offset applied (as reference)
    __shared__ int   slab[PRE_K];
    __shared__ int   skeep[PRE_K];
    __shared__ int   swsum[16];

    int img = blockIdx.x; int tid = threadIdx.x;

    // candidates: j = p*8 + (c-1), c in 1..8
    for (int j = tid; j < 4096; j += 512) {
        int p = j >> 3, c = (j & 7) + 1;
        int n = img * 512 + p;
        float s = g_scores[n * NCLS + c];
        const float* bb = g_boxes + (size_t)(n * NCLS + c) * 4;
        bool valid = (s > 0.05f) && ((bb[2] - bb[0]) >= 0.01f) && ((bb[3] - bb[1]) >= 0.01f);
        skey[j] = valid ? s : -INFINITY;
        sidx[j] = j;
    }
    __syncthreads();

    // bitonic sort, best-first (score desc, index asc on ties -> matches top_k)
    for (int k = 2; k <= 4096; k <<= 1) {
        for (int j2 = k >> 1; j2 > 0; j2 >>= 1) {
            for (int i = tid; i < 4096; i += 512) {
                int ixj = i ^ j2;
                if (ixj > i) {
                    float ka = skey[i], kb = skey[ixj];
                    int ia = sidx[i], ib = sidx[ixj];
                    bool a_first = (ka > kb) || (ka == kb && ia < ib);
                    bool up = ((i & k) == 0);
                    if (up ? !a_first : a_first) {
                        skey[i] = kb; skey[ixj] = ka;
                        sidx[i] = ib; sidx[ixj] = ia;
                    }
                }
            }
            __syncthreads();
        }
    }

    // top-512: stage offset boxes (reference computes IoU on boxes + label*641)
    if (tid < PRE_K) {
        float s = skey[tid];
        int j = sidx[tid];
        int p = j >> 3, c = (j & 7) + 1;
        int n = img * 512 + p;
        const float* bb = g_boxes + (size_t)(n * NCLS + c) * 4;
        float off = 641.0f * (float)c;
        sbox[tid * 4 + 0] = bb[0] + off;
        sbox[tid * 4 + 1] = bb[1] + off;
        sbox[tid * 4 + 2] = bb[2] + off;
        sbox[tid * 4 + 3] = bb[3] + off;
        slab[tid] = c;
        skeep[tid] = (s != -INFINITY) ? 1 : 0;
    }
    __syncthreads();

    // greedy NMS (sequential over i, parallel over j = tid)
    for (int i = 0; i < PRE_K; i++) {
        if (skeep[i]) {
            int j = tid;
            if (j > i && skeep[j]) {
                float ax0 = sbox[i*4], ay0 = sbox[i*4+1], ax1 = sbox[i*4+2], ay1 = sbox[i*4+3];
                float bx0 = sbox[j*4], by0 = sbox[j*4+1], bx1 = sbox[j*4+2], by1 = sbox[j*4+3];
                float areaA = (ax1 - ax0) * (ay1 - ay0);
                float areaB = (bx1 - bx0) * (by1 - by0);
                float iw = fmaxf(fminf(ax1, bx1) - fmaxf(ax0, bx0), 0.f);
                float ih = fmaxf(fminf(ay1, by1) - fmaxf(ay0, by0), 0.f);
                float inter = iw * ih;
                float iou = inter / fmaxf(areaA + areaB - inter, 1e-8f);
                if (iou > 0.5f) skeep[j] = 0;
            }
        }
        __syncthreads();
    }

    // rank of kept entries (order preserved = descending score = reference top_k)
    int keepflag = (tid < PRE_K) ? skeep[tid] : 0;
    unsigned mask = __ballot_sync(0xffffffffu, keepflag != 0);
    int lane = tid & 31, wid = tid >> 5;
    if (lane == 0) swsum[wid] = __popc(mask);
    __syncthreads();
    int base = 0;
    for (int w = 0; w < wid; w++) base += swsum[w];
    int rank = base + __popc(mask & ((1u << lane) - 1u));

    float* dbx = d_out + O_BOX + (size_t)img * DETS * 4;
    float* dsc = d_out + O_SCO + (size_t)img * DETS;
    float* dlb = d_out + O_LAB + (size_t)img * DETS;
    float* dvl = d_out + O_VAL + (size_t)img * DETS;
    for (int i = tid; i < DETS; i += 512) {
        dbx[i*4+0] = 0.f; dbx[i*4+1] = 0.f; dbx[i*4+2] = 0.f; dbx[i*4+3] = 0.f;
        dsc[i] = 0.f; dlb[i] = 0.f; dvl[i] = 0.f;
    }
    __syncthreads();
    if (keepflag && rank < DETS) {
        int j = sidx[tid];
        int p = j >> 3, c = (j & 7) + 1;
        int n = img * 512 + p;
        const float* bb = g_boxes + (size_t)(n * NCLS + c) * 4;
        dbx[rank*4+0] = bb[0]; dbx[rank*4+1] = bb[1];
        dbx[rank*4+2] = bb[2]; dbx[rank*4+3] = bb[3];
        dsc[rank] = skey[tid];
        dlb[rank] = (float)c;
        dvl[rank] = 1.0f;
    }
}

// ---------------- launch ----------------
extern "C" void kernel_launch(void* const* d_in, const int* in_sizes, int n_in,
                              void* d_out, int out_size) {
    const float* feats     = (const float*)d_in[0];
    const float* proposals = (const float*)d_in[1];
    const float* w1        = (const float*)d_in[2];
    const float* w2        = (const float*)d_in[3];
    const float* wd        = (const float*)d_in[4];
    const float* cls_w     = (const float*)d_in[5];
    const float* cls_b     = (const float*)d_in[6];
    const float* reg_w     = (const float*)d_in[7];
    const float* reg_b     = (const float*)d_in[8];
    float* out = (float*)d_out;

    cudaFuncSetAttribute(conv1_kernel, cudaFuncAttributeMaxDynamicSharedMemorySize, SMEM_BYTES);
    cudaFuncSetAttribute(conv2_kernel, cudaFuncAttributeMaxDynamicSharedMemorySize, SMEM_BYTES);

    tr_w1<<<(CIN * 9 * CMID + 255) / 256, 256>>>(w1);
    tr_w2<<<(CMID * 9 * CMID + 255) / 256, 256>>>(w2);
    tr_wd<<<(CIN * CMID + 255) / 256, 256>>>(wd);

    conv1_kernel<<<dim3(NSAMP, 2), 256, SMEM_BYTES>>>(feats);
    conv2_kernel<<<dim3(NSAMP, 2), 256, SMEM_BYTES>>>(feats, out);

    head_kernel<<<NSAMP, 256>>>(cls_w, cls_b, reg_w, reg_b, out);
    decode_kernel<<<NSAMP, 32>>>(proposals);
    nms_kernel<<<2, 512>>>(out);
}